// round 5
// baseline (speedup 1.0000x reference)
#include <cuda_runtime.h>
#include <cstdint>

// VoltageNet: B=512 batches, T=8192 timesteps.
// One CTA per batch, 512 threads, 16 timesteps/thread.
//  - UH state is provably 0 (LB==UB==0 for mMH and KH) -> only U1 affine recurrence.
//  - SOC: block prefix sum.  U1: block affine-compose scan.
//  - Per-step MLP + OCV with fast intrinsics (expf/logf/tanh.approx).

#define TT 8192
#define NT 512
#define LL 16
#define FULL 0xFFFFFFFFu

__device__ __forceinline__ float tanh_fast(float x) {
    float y; asm("tanh.approx.f32 %0, %1;" : "=f"(y) : "f"(x)); return y;
}
__device__ __forceinline__ float sigmoid_f(float z) {
    return __fdividef(1.0f, 1.0f + __expf(-z));
}
__device__ __forceinline__ float softplus_f(float x) {
    return fmaxf(x, 0.0f) + __logf(1.0f + __expf(-fabsf(x)));
}

__global__ __launch_bounds__(NT, 1)
void voltage_kernel(const float* __restrict__ X, const float* __restrict__ SC,
                    const float* __restrict__ W1g, const float* __restrict__ b1g,
                    const float* __restrict__ W2g, const float* __restrict__ b2g,
                    float* __restrict__ out)
{
    // skewed staging buffer: slot(t) = t + (t>>4)  (conflict-free both phases)
    __shared__ float sV[TT + TT / 16];
    __shared__ float sWS[16];              // SOC warp offsets
    __shared__ float sWA[16], sWB[16];     // affine warp aggregates
    __shared__ float sTr[16];
    __shared__ float sW10[6], sC1[6], sW2[24], sB2[4];
    __shared__ float sTmean, sU10;

    const int tid  = threadIdx.x;
    const int lane = tid & 31;
    const int wid  = tid >> 5;
    const int b    = blockIdx.x;
    const int base = tid * LL;

    const float Q  = SC[2 * b + 0];
    const float R0 = SC[2 * b + 1];

    // stage MLP constants to smem (cols 0,1,5,6 of W2)
    if (tid < 6) sW10[tid] = W1g[tid];
    if (tid >= 32 && tid < 56) {
        int i = (tid - 32) >> 2, c = (tid - 32) & 3;
        const int col[4] = {0, 1, 5, 6};
        sW2[tid - 32] = W2g[i * 7 + col[c]];
    }
    if (tid >= 64 && tid < 68) {
        const int col[4] = {0, 1, 5, 6};
        sB2[tid - 64] = b2g[col[tid - 64]];
    }

    // ---------- phase 0: load own 16 timesteps (+1 boundary) ----------
    float4 fv[12];
    const float4* px = reinterpret_cast<const float4*>(X + ((size_t)b * TT + base) * 3);
#pragma unroll
    for (int i = 0; i < 12; i++) fv[i] = px[i];
    const float* f = reinterpret_cast<const float*>(fv);

    float t16, I16;
    if (tid < NT - 1) {
        float2 e = *reinterpret_cast<const float2*>(X + ((size_t)b * TT + base + LL) * 3);
        t16 = e.x; I16 = e.y;
    } else {
        t16 = f[45]; I16 = f[46];   // clamp -> ds[15]=0, a[15]=1, b[15]=0 naturally
    }

    float Iv[LL + 1];
    float ds[LL];
    float tsum = 0.0f;
    const float invC = 1.0f / 36000.0f;   // 1/(2*3600*QN), QN=5
#pragma unroll
    for (int k = 0; k < LL; k++) { Iv[k] = f[3 * k + 1]; tsum += f[3 * k + 2]; }
    Iv[LL] = I16;
#pragma unroll
    for (int k = 0; k < LL; k++) {
        float tn = (k < LL - 1) ? f[3 * (k + 1)] : t16;
        ds[k] = (Iv[k + 1] + Iv[k]) * (tn - f[3 * k]) * invC;
    }

    float dsum = 0.0f;
#pragma unroll
    for (int k = 0; k < LL; k++) dsum += ds[k];

    // warp-level: inclusive scan of dsum, reduce tsum
    float v = dsum;
#pragma unroll
    for (int o = 1; o < 32; o <<= 1) {
        float n = __shfl_up_sync(FULL, v, o);
        if (lane >= o) v += n;
    }
    float excl = __shfl_up_sync(FULL, v, 1);
    if (lane == 0) excl = 0.0f;
#pragma unroll
    for (int o = 16; o > 0; o >>= 1) tsum += __shfl_down_sync(FULL, tsum, o);
    if (lane == 31) sWS[wid] = v;
    if (lane == 0)  sTr[wid] = tsum;
    __syncthreads();

    if (tid < 32) {
        // scan 16 warp sums -> exclusive offsets
        float w = (lane < 16) ? sWS[lane] : 0.0f;
#pragma unroll
        for (int o = 1; o < 16; o <<= 1) {
            float n = __shfl_up_sync(FULL, w, o);
            if (lane >= o) w += n;
        }
        float e = __shfl_up_sync(FULL, w, 1);
        if (lane == 0) e = 0.0f;
        if (lane < 16) sWS[lane] = e;
        // Tmean
        float ts = (lane < 16) ? sTr[lane] : 0.0f;
#pragma unroll
        for (int o = 16; o > 0; o >>= 1) ts += __shfl_down_sync(FULL, ts, o);
        if (lane == 0) sTmean = ts * (1.0f / TT);
    }
    __syncthreads();
    if (tid < 6)
        sC1[tid] = fmaf(R0, W1g[6 + tid], fmaf(sTmean, W1g[12 + tid], b1g[tid]));
    __syncthreads();

    // ---------- phase 1: per-step MLP + theta + OCV + scan coefficients ----------
    float soc = fmaf(Q, 0.2f, sWS[wid] + excl);   // Q/QN + prefix
    float av[LL], bv[LL];
#pragma unroll
    for (int k = 0; k < LL; k++) {
        float p0 = sB2[0], p1 = sB2[1], p5 = sB2[2], p6 = sB2[3];
#pragma unroll
        for (int j = 0; j < 6; j++) {
            float h = softplus_f(fmaf(soc, sW10[j], sC1[j]));
            p0 = fmaf(h, sW2[j * 4 + 0], p0);
            p1 = fmaf(h, sW2[j * 4 + 1], p1);
            p5 = fmaf(h, sW2[j * 4 + 2], p5);
            p6 = fmaf(h, sW2[j * 4 + 3], p6);
        }
        float R1 = 0.04f * sigmoid_f(0.01f * p0);
        float C  = 1e-6f * sigmoid_f(0.01f * p1);
        float ox = fmaf(0.79764f, sigmoid_f(0.01f * p5), 0.04236f);
        float oy = fmaf(0.82504f, sigmoid_f(0.01f * p6), 0.023f);

        float up = 4.4167f + oy * (-1.6518f + oy * (1.6225f + oy * (-2.0843f + oy * (3.5146f + oy * (-2.2166f)))));
        up -= 4.0f * __expf(fmaf(109.451f, oy, -100.006f));
        float un = 0.063f + 0.8f * __expf(-75.0f * (ox + 0.001f));
        un -= 0.012f  * tanh_fast(fmaf(ox, 62.5f, -7.9375f));
        un -= 0.0118f * tanh_fast(fmaf(ox, 62.5f, -9.6875f));
        un -= 0.0035f * tanh_fast(fmaf(ox, 50.0f, -11.0f));
        un -= 0.0095f * tanh_fast(fmaf(ox, 76.923076923f, -14.6153846154f));
        un -= 0.0145f * tanh_fast(fmaf(ox, 50.0f, -24.5f));
        un -= 0.08f   * tanh_fast(fmaf(ox, 18.1818181818f, -18.7272727273f));

        int t = base + k;
        sV[t + (t >> 4)] = up - un;                  // OCV

        float dt = Iv[k + 1] - Iv[k];
        float g  = dt * C;
        av[k] = 1.0f - g;
        bv[k] = g * R1 * Iv[k];
        soc += ds[k];
    }

    if (tid == 0) {
        // theta2 (OCV_U) at t=0 for U1(0)
        float soc0 = Q * 0.2f;
        float p2 = b2g[2];
#pragma unroll
        for (int j = 0; j < 6; j++) {
            float h = softplus_f(fmaf(soc0, sW10[j], sC1[j]));
            p2 = fmaf(h, W2g[j * 7 + 2], p2);
        }
        float th2 = fmaf(0.75f, sigmoid_f(0.01f * p2), 0.05f);
        sU10 = -th2 - Iv[0] * R0;
    }
    __syncthreads();

    // ---------- phase 2: block affine scan (a,b) composition ----------
    float A = 1.0f, B = 0.0f;
#pragma unroll
    for (int k = 0; k < LL; k++) { B = fmaf(av[k], B, bv[k]); A *= av[k]; }
#pragma unroll
    for (int o = 1; o < 32; o <<= 1) {
        float Ao = __shfl_up_sync(FULL, A, o);
        float Bo = __shfl_up_sync(FULL, B, o);
        if (lane >= o) { B = fmaf(A, Bo, B); A = A * Ao; }
    }
    float Ax = __shfl_up_sync(FULL, A, 1);
    float Bx = __shfl_up_sync(FULL, B, 1);
    if (lane == 0) { Ax = 1.0f; Bx = 0.0f; }
    if (lane == 31) { sWA[wid] = A; sWB[wid] = B; }
    __syncthreads();
    if (tid < 32) {
        float wA = (lane < 16) ? sWA[lane] : 1.0f;
        float wB = (lane < 16) ? sWB[lane] : 0.0f;
#pragma unroll
        for (int o = 1; o < 16; o <<= 1) {
            float Ao = __shfl_up_sync(FULL, wA, o);
            float Bo = __shfl_up_sync(FULL, wB, o);
            if (lane >= o) { wB = fmaf(wA, Bo, wB); wA = wA * Ao; }
        }
        float eA = __shfl_up_sync(FULL, wA, 1);
        float eB = __shfl_up_sync(FULL, wB, 1);
        if (lane == 0) { eA = 1.0f; eB = 0.0f; }
        if (lane < 16) { sWA[lane] = eA; sWB[lane] = eB; }
    }
    __syncthreads();
    float wA = sWA[wid], wB = sWB[wid];
    float EA = Ax * wA;
    float EB = fmaf(Ax, wB, Bx);
    float U1 = fmaf(EA, sU10, EB);

    // ---------- phase 3: finalize + coalesced store ----------
#pragma unroll
    for (int k = 0; k < LL; k++) {
        int t = base + k;
        sV[t + (t >> 4)] = sV[t + (t >> 4)] + U1 + Iv[k] * R0;
        U1 = fmaf(av[k], U1, bv[k]);
    }
    __syncthreads();
    float* ob = out + (size_t)b * TT;
#pragma unroll
    for (int i = 0; i < LL; i++) {
        int idx = tid + i * NT;
        ob[idx] = sV[idx + (idx >> 4)];
    }
}

extern "C" void kernel_launch(void* const* d_in, const int* in_sizes, int n_in,
                              void* d_out, int out_size)
{
    const float* X  = (const float*)d_in[0];
    const float* SC = (const float*)d_in[1];
    const float* W1 = (const float*)d_in[2];
    const float* b1 = (const float*)d_in[3];
    const float* W2 = (const float*)d_in[4];
    const float* b2 = (const float*)d_in[5];
    int B = in_sizes[1] / 2;                 // SC is (B,2)
    voltage_kernel<<<B, NT>>>(X, SC, W1, b1, W2, b2, (float*)d_out);
}